// round 9
// baseline (speedup 1.0000x reference)
#include <cuda_runtime.h>
#include <math_constants.h>

#define NB 4
#define NN 16384
#define NM 512
#define NC 128
#define NK 16
#define NL 6
#define NSTEPS 5
#define GG 64
#define G3 (GG*GG*GG)
#define GSP (G3+4)
#define CCAP 1024

// ---------------- scratch (device globals: no allocations allowed) ----------
__device__ float g_feats[NB*NN*NC];
__device__ float g_Qf[NB*NN*NC];
__device__ float g_Gf[NB*NN*NC];
__device__ __align__(16) float g_pos4[NB*NN*4];
__device__ float g_wsel[NB*NM*NL*NC];
__device__ float g_rout[2][NB*NM*NL*NC];
__device__ float g_disp[NB*NM*3];
__device__ unsigned g_bboxi[NB][6];
__device__ __align__(16) int g_cellcnt[NB][G3];
__device__ __align__(16) int g_cellstart[NB][GSP];   // padded row: stride % 16B == 0
__device__ __align__(16) float4 g_spos[NB*NN];

// ---------------- f32x2 packed helpers --------------------------------------
__device__ __forceinline__ void dfma2(unsigned long long& d,
                                      unsigned long long a,
                                      unsigned long long b) {
    asm("fma.rn.f32x2 %0, %1, %2, %0;" : "+l"(d) : "l"(a), "l"(b));
}
__device__ __forceinline__ unsigned long long packdup(float w) {
    unsigned long long r;
    asm("mov.b64 %0, {%1, %1};" : "=l"(r) : "f"(w));
    return r;
}
__device__ __forceinline__ void unpack2(unsigned long long a, float& lo, float& hi) {
    asm("mov.b64 {%0, %1}, %2;" : "=f"(lo), "=f"(hi) : "l"(a));
}

// ---------------- order-preserving float<->uint encoding --------------------
__device__ __forceinline__ unsigned encf(float f) {
    int i = __float_as_int(f);
    return (i >= 0) ? ((unsigned)i | 0x80000000u) : ~(unsigned)i;
}
__device__ __forceinline__ float decf(unsigned k) {
    return __int_as_float((k & 0x80000000u) ? (int)(k ^ 0x80000000u) : (int)~k);
}

struct BBox { float mnx, mny, mnz, ivx, ivy, ivz, hmin; };
__device__ __forceinline__ BBox load_bbox(int b) {
    BBox bb;
    bb.mnx = decf(g_bboxi[b][0]); bb.mny = decf(g_bboxi[b][1]); bb.mnz = decf(g_bboxi[b][2]);
    float rx = fmaxf(decf(g_bboxi[b][3]) - bb.mnx, 1e-6f);
    float ry = fmaxf(decf(g_bboxi[b][4]) - bb.mny, 1e-6f);
    float rz = fmaxf(decf(g_bboxi[b][5]) - bb.mnz, 1e-6f);
    bb.ivx = (float)GG / rx; bb.ivy = (float)GG / ry; bb.ivz = (float)GG / rz;
    bb.hmin = fminf(rx, fminf(ry, rz)) * (1.0f / GG);
    return bb;
}
__device__ __forceinline__ int clampg(int v) { return min(GG-1, max(0, v)); }
__device__ __forceinline__ int cell_of(const BBox& bb, float x, float y, float z,
                                       int& cx, int& cy, int& cz) {
    cx = clampg((int)((x - bb.mnx) * bb.ivx));
    cy = clampg((int)((y - bb.mny) * bb.ivy));
    cz = clampg((int)((z - bb.mnz) * bb.ivz));
    return (cz*GG + cy)*GG + cx;
}
__device__ __forceinline__ void bbox_reset(int gid) {
    if (gid < NB*6) ((unsigned*)g_bboxi)[gid] = (gid % 6) < 3 ? 0xFFFFFFFFu : 0u;
}

// ---------------- init ------------------------------------------------------
__global__ void init_pos_kernel(const float* __restrict__ xyz) {
    int i = blockIdx.x * blockDim.x + threadIdx.x;
    bbox_reset(i);
    if (i < NB*NN) {
        float x = xyz[i*3+0], y = xyz[i*3+1], z = xyz[i*3+2];
        *(float4*)&g_pos4[(size_t)i*4] = make_float4(x, y, z, 0.f);
    }
}

// ---------------- grid prep: zero histogram + bbox atomic reduce ------------
__global__ void gridprep_kernel() {
    __shared__ unsigned smn[3][8], smx[3][8];
    int tid = threadIdx.x;
    int gid = blockIdx.x * 256 + tid;           // 65536 threads
    int4 z4 = make_int4(0,0,0,0);
    int4* cc = (int4*)g_cellcnt;                // NB*G3/4 = 262144 int4
    cc[gid] = z4; cc[gid + 65536] = z4; cc[gid + 131072] = z4; cc[gid + 196608] = z4;
    int b = blockIdx.x >> 6;
    int i = (blockIdx.x & 63) * 256 + tid;
    const float4 p = *(const float4*)&g_pos4[((size_t)b*NN + i) * 4];
    unsigned ex = encf(p.x), ey = encf(p.y), ez = encf(p.z);
    unsigned nx = ex, ny = ey, nz = ez;
    #pragma unroll
    for (int off = 16; off; off >>= 1) {
        nx = min(nx, __shfl_xor_sync(0xffffffffu, nx, off));
        ny = min(ny, __shfl_xor_sync(0xffffffffu, ny, off));
        nz = min(nz, __shfl_xor_sync(0xffffffffu, nz, off));
        ex = max(ex, __shfl_xor_sync(0xffffffffu, ex, off));
        ey = max(ey, __shfl_xor_sync(0xffffffffu, ey, off));
        ez = max(ez, __shfl_xor_sync(0xffffffffu, ez, off));
    }
    int warp = tid >> 5;
    if ((tid & 31) == 0) {
        smn[0][warp] = nx; smn[1][warp] = ny; smn[2][warp] = nz;
        smx[0][warp] = ex; smx[1][warp] = ey; smx[2][warp] = ez;
    }
    __syncthreads();
    if (tid < 3) {
        unsigned mn = 0xFFFFFFFFu, mx = 0u;
        #pragma unroll
        for (int w = 0; w < 8; w++) { mn = min(mn, smn[tid][w]); mx = max(mx, smx[tid][w]); }
        atomicMin(&g_bboxi[b][tid], mn);
        atomicMax(&g_bboxi[b][tid + 3], mx);
    }
}

__global__ void hist_kernel() {
    int gid = blockIdx.x * 256 + threadIdx.x;
    int b = gid >> 14, i = gid & (NN-1);
    BBox bb = load_bbox(b);
    const float4 p = *(const float4*)&g_pos4[((size_t)b*NN + i) * 4];
    int cx, cy, cz;
    int c = cell_of(bb, p.x, p.y, p.z, cx, cy, cz);
    atomicAdd(&g_cellcnt[b][c], 1);
}

// ---------------- exclusive scan over G3 cells (1 block / batch) -----------
__global__ void scan_kernel() {
    __shared__ int ss[1024];
    int b = blockIdx.x, t = threadIdx.x;
    int base = t * (G3/1024);                   // 256 cells / thread
    const int4* cc = (const int4*)&g_cellcnt[b][base];
    int s = 0;
    for (int k = 0; k < 64; k++) { int4 v = cc[k]; s += v.x + v.y + v.z + v.w; }
    int mysum = s;
    ss[t] = s; __syncthreads();
    for (int off = 1; off < 1024; off <<= 1) {
        int v = (t >= off) ? ss[t - off] : 0;
        __syncthreads();
        ss[t] += v;
        __syncthreads();
    }
    int running = ss[t] - mysum;
    int4* st4 = (int4*)&g_cellstart[b][base];
    int4* cn4 = (int4*)&g_cellcnt[b][base];
    for (int k = 0; k < 64; k++) {
        int4 v = cc[k];
        int4 w;
        w.x = running; running += v.x;
        w.y = running; running += v.y;
        w.z = running; running += v.z;
        w.w = running; running += v.w;
        st4[k] = w; cn4[k] = w;
    }
    if (t == 0) g_cellstart[b][G3] = NN;
}

__global__ void scatterpts_kernel() {
    int gid = blockIdx.x * 256 + threadIdx.x;
    int b = gid >> 14, i = gid & (NN-1);
    BBox bb = load_bbox(b);
    const float4 p = *(const float4*)&g_pos4[((size_t)b*NN + i) * 4];
    int cx, cy, cz;
    int c = cell_of(bb, p.x, p.y, p.z, cx, cy, cz);
    int slot = atomicAdd(&g_cellcnt[b][c], 1);
    g_spos[(size_t)b*NN + slot] = make_float4(p.x, p.y, p.z, __int_as_float(i));
}

// ---------------- encoder ---------------------------------------------------
__global__ void encode_kernel(const float* __restrict__ xyz,
                              const float* __restrict__ w1, const float* __restrict__ b1,
                              const float* __restrict__ w2, const float* __restrict__ b2) {
    __shared__ float h[4][64];
    int tid = threadIdx.x;
    int p0 = blockIdx.x * 4;
    for (int i = tid; i < 4*64; i += 128) {
        int pt = i >> 6, j = i & 63;
        const float* x = xyz + (size_t)(p0 + pt) * 3;
        float v = b1[j] + w1[j*3+0]*x[0] + w1[j*3+1]*x[1] + w1[j*3+2]*x[2];
        h[pt][j] = fmaxf(v, 0.f);
    }
    __syncthreads();
    float acc[4];
    #pragma unroll
    for (int p = 0; p < 4; p++) acc[p] = b2[tid];
    const float4* wr = (const float4*)(w2 + (size_t)tid * 64);
    #pragma unroll
    for (int j4 = 0; j4 < 16; j4++) {
        float4 w = wr[j4];
        #pragma unroll
        for (int p = 0; p < 4; p++) {
            float4 hv = *(const float4*)&h[p][4*j4];
            acc[p] += w.x*hv.x + w.y*hv.y + w.z*hv.z + w.w*hv.w;
        }
    }
    #pragma unroll
    for (int p = 0; p < 4; p++)
        g_feats[(size_t)(p0 + p) * NC + tid] = acc[p];
}

// ---------------- beta/gamma projections (f32x2 point-pairs) ----------------
__global__ void proj_kernel(const float* __restrict__ bw, const float* __restrict__ bb,
                            const float* __restrict__ gw, const float* __restrict__ gb) {
    __shared__ __align__(8) float xs[128*16];      // xs[ch*16 + p]
    int c = threadIdx.x;                           // 128 threads
    size_t base = (size_t)blockIdx.x * 16 * 128;
    for (int i = c; i < 16*128; i += 128) {
        int p = i >> 7, ch = i & 127;
        xs[ch*16 + p] = g_feats[base + i];
    }
    __syncthreads();
    unsigned long long accQ[8], accG[8];
    unsigned long long bq = packdup(bb[c]), bg = packdup(gb[c]);
    #pragma unroll
    for (int p = 0; p < 8; p++) { accQ[p] = bq; accG[p] = bg; }
    const float4* wq = (const float4*)(bw + (size_t)c * 128);
    const float4* wg = (const float4*)(gw + (size_t)c * 128);
    for (int j4 = 0; j4 < 32; j4++) {
        float4 a = wq[j4];
        float4 g = wg[j4];
        float aa[4] = {a.x, a.y, a.z, a.w};
        float gg2[4] = {g.x, g.y, g.z, g.w};
        #pragma unroll
        for (int jj = 0; jj < 4; jj++) {
            int ch = 4*j4 + jj;
            unsigned long long wa = packdup(aa[jj]);
            unsigned long long wgv = packdup(gg2[jj]);
            const unsigned long long* x2 = (const unsigned long long*)&xs[ch*16];
            #pragma unroll
            for (int p = 0; p < 8; p++) {
                dfma2(accQ[p], x2[p], wa);
                dfma2(accG[p], x2[p], wgv);
            }
        }
    }
    #pragma unroll
    for (int p = 0; p < 8; p++) {
        float q0, q1, g0, g1;
        unpack2(accQ[p], q0, q1);
        unpack2(accG[p], g0, g1);
        g_Qf[base + (size_t)(2*p)*128 + c]   = q0;
        g_Qf[base + (size_t)(2*p+1)*128 + c] = q1;
        g_Gf[base + (size_t)(2*p)*128 + c]   = g0;
        g_Gf[base + (size_t)(2*p+1)*128 + c] = g1;
    }
}

// ---------------- KNN helpers ----------------------------------------------
__device__ __forceinline__ unsigned long long knn_select17(unsigned long long* buf,
                                                           int n, int lane) {
    unsigned long long mykey = ~0ull;
    for (int j = 0; j < 17; j++) {
        unsigned long long local = ~0ull; int slot = -1;
        for (int s2 = lane; s2 < n; s2 += 32) {
            unsigned long long v = buf[s2];
            if (v < local) { local = v; slot = s2; }
        }
        unsigned long long mv = local;
        #pragma unroll
        for (int off = 16; off; off >>= 1) {
            unsigned long long o = __shfl_xor_sync(0xffffffffu, mv, off);
            mv = (o < mv) ? o : mv;
        }
        if (local == mv && slot >= 0) buf[slot] = ~0ull;
        if (lane == j) mykey = mv;
        __syncwarp();
    }
    return mykey;
}

__device__ __forceinline__ void knn_compact(unsigned long long* buf, int& n, int lane) {
    unsigned long long mk = knn_select17(buf, n, lane);
    __syncwarp();
    if (lane < 17) buf[lane] = mk;
    n = 17;
    __syncwarp();
}

__device__ __forceinline__ unsigned long long mkkey(const float4& p,
                                                    float qx, float qy, float qz) {
    float dx = p.x - qx, dy = p.y - qy, dz = p.z - qz;
    float d = fmaf(dz, dz, fmaf(dy, dy, dx*dx));
    return ((unsigned long long)__float_as_uint(d) << 32) | (unsigned)__float_as_int(p.w);
}

__device__ void knn_append_batch(unsigned long long* buf, int& n,
                                 int s1, int e1, int s2, int e2,
                                 const float4* __restrict__ sp,
                                 float qx, float qy, float qz, int lane) {
    int cnt = (e1 - s1) + (e2 - s2);
    int off = cnt;
    #pragma unroll
    for (int d = 1; d < 32; d <<= 1) {
        int v = __shfl_up_sync(0xffffffffu, off, d);
        if (lane >= d) off += v;
    }
    int total = __shfl_sync(0xffffffffu, off, 31);
    off -= cnt;
    if (n + total > CCAP) knn_compact(buf, n, lane);
    if (n + total <= CCAP) {
        int o = n + off;
        for (int k = 0; k < e1 - s1; k++) buf[o + k] = mkkey(sp[s1 + k], qx, qy, qz);
        o += e1 - s1;
        for (int k = 0; k < e2 - s2; k++) buf[o + k] = mkkey(sp[s2 + k], qx, qy, qz);
        n += total;
        __syncwarp();
    } else {
        // exact cooperative fallback (only if one batch alone exceeds CCAP)
        for (int lt = 0; lt < 32; lt++) {
            int bs0 = __shfl_sync(0xffffffffu, s1, lt), be0 = __shfl_sync(0xffffffffu, e1, lt);
            int bs1 = __shfl_sync(0xffffffffu, s2, lt), be1 = __shfl_sync(0xffffffffu, e2, lt);
            #pragma unroll
            for (int q = 0; q < 2; q++) {
                int c = q ? bs1 : bs0, e = q ? be1 : be0;
                while (c < e) {
                    if (n >= CCAP - 32) knn_compact(buf, n, lane);
                    int chunk = min(e - c, CCAP - n);
                    for (int k = lane; k < chunk; k += 32)
                        buf[n + k] = mkkey(sp[c + k], qx, qy, qz);
                    n += chunk; c += chunk;
                    __syncwarp();
                }
            }
        }
    }
}

// ---------------- fused per-step selector: grid KNN + gumbel argmax --------
__global__ __launch_bounds__(128)
void knn_step_kernel(const int* __restrict__ start,
                     const float* __restrict__ gumbel, int t) {
    __shared__ __align__(8) unsigned long long cbuf[4][CCAP];
    __shared__ int sknn[4][NK];
    int warp = threadIdx.x >> 5, lane = threadIdx.x & 31;
    int b = blockIdx.x / (NM/4);
    int m = (blockIdx.x % (NM/4)) * 4 + warp;
    int gw = b*NM + m;
    int qidx = start[gw];
    const float4* pos = (const float4*)(g_pos4 + (size_t)b * NN * 4);
    const float4* sp  = g_spos + (size_t)b * NN;
    const int* cs = g_cellstart[b];
    const float* Gf = g_Gf + (size_t)b*NN*NC;
    unsigned long long* buf = cbuf[warp];
    BBox bb = load_bbox(b);

    {   // walk[0] = feats[start]
        const float* fr = g_feats + ((size_t)b*NN + qidx) * NC;
        float* wr = g_wsel + (size_t)gw * NL * NC;
        #pragma unroll
        for (int r = 0; r < 4; r++) wr[lane + 32*r] = fr[lane + 32*r];
    }

    for (int l = 0; l < NL-1; l++) {
        float4 qp = pos[qidx];
        float qx = qp.x, qy = qp.y, qz = qp.z;
        int cx, cy, cz;
        cell_of(bb, qx, qy, qz, cx, cy, cz);
        int n = 0;

        // collect rings 0..2 (5x5x5 cube): 25 rows, one per lane, parallel cs
        {
            int s1 = 0, e1 = 0;
            if (lane < 25) {
                int dz = lane/5 - 2, dy = lane%5 - 2;
                int z = cz + dz, y = cy + dy;
                if ((unsigned)z < GG && (unsigned)y < GG) {
                    int rowb = (z*GG + y)*GG;
                    int xlo = max(cx-2, 0), xhi = min(cx+2, GG-1);
                    s1 = cs[rowb + xlo]; e1 = cs[rowb + xhi + 1];
                }
            }
            knn_append_batch(buf, n, s1, e1, 0, 0, sp, qx, qy, qz, lane);
        }
        unsigned long long mykey = knn_select17(buf, n, lane);
        __syncwarp();
        if (lane < 17) buf[lane] = mykey;
        n = 17; __syncwarp();
        unsigned taub = (unsigned)(__shfl_sync(0xffffffffu, mykey, 16) >> 32);

        int R = 2;
        while (true) {
            float bnd = (float)R * bb.hmin;
            unsigned ub = __float_as_uint(bnd * bnd);
            if (taub < ub) break;          // all unscanned cells strictly farther
            R++;
            if (R >= 2*GG) break;
            int W2 = 2*R + 1, T = W2*W2;
            for (int base = 0; base < T; base += 32) {
                int ti = base + lane;
                int s1=0, e1=0, s2=0, e2=0;
                if (ti < T) {
                    int dz = ti / W2 - R, dy = ti % W2 - R;
                    int z = cz + dz, y = cy + dy;
                    if ((unsigned)z < GG && (unsigned)y < GG) {
                        int rowb = (z*GG + y)*GG;
                        if (dz == -R || dz == R || dy == -R || dy == R) {
                            int xlo = max(cx-R, 0), xhi = min(cx+R, GG-1);
                            s1 = cs[rowb + xlo]; e1 = cs[rowb + xhi + 1];
                        } else {
                            int xl = cx - R;
                            if (xl >= 0) { s1 = cs[rowb + xl]; e1 = cs[rowb + xl + 1]; }
                            int xh = cx + R;
                            if (xh < GG) { s2 = cs[rowb + xh]; e2 = cs[rowb + xh + 1]; }
                        }
                    }
                }
                knn_append_batch(buf, n, s1, e1, s2, e2, sp, qx, qy, qz, lane);
            }
            mykey = knn_select17(buf, n, lane);
            __syncwarp();
            if (lane < 17) buf[lane] = mykey;
            n = 17; __syncwarp();
            taub = (unsigned)(__shfl_sync(0xffffffffu, mykey, 16) >> 32);
        }

        // lanes 0..16 hold sorted top-17 (lex (d,idx)); drop lane0 (= self)
        if (lane >= 1 && lane < 17)
            sknn[warp][lane - 1] = (int)(unsigned)(mykey & 0xFFFFFFFFull);
        __syncwarp();

        // logits + gumbel argmax
        const float* Q = g_Qf + ((size_t)b*NN + qidx) * NC;
        float qv0 = Q[lane], qv1 = Q[lane+32], qv2 = Q[lane+64], qv3 = Q[lane+96];
        float pk[16];
        #pragma unroll
        for (int k = 0; k < 16; k++) {
            const float* gr = Gf + (size_t)sknn[warp][k] * NC;
            pk[k] = qv0*gr[lane] + qv1*gr[lane+32] + qv2*gr[lane+64] + qv3*gr[lane+96];
        }
        #pragma unroll
        for (int k = 0; k < 16; k++) {
            #pragma unroll
            for (int off = 16; off; off >>= 1)
                pk[k] += __shfl_xor_sync(0xffffffffu, pk[k], off);
        }
        const float* gm = gumbel + ((((size_t)t*(NL-1) + l)*NB + b)*NM + m) * NK;
        float best = -CUDART_INF_F; int bk = 0;
        #pragma unroll
        for (int k = 0; k < 16; k++) {
            float s = pk[k] / 11.313708498984761f + gm[k];
            if (s > best) { best = s; bk = k; }
        }
        qidx = sknn[warp][bk];
        const float* fr = g_feats + ((size_t)b*NN + qidx) * NC;
        float* wr = g_wsel + ((size_t)gw * NL + (l + 1)) * NC;
        #pragma unroll
        for (int r = 0; r < 4; r++) wr[lane + 32*r] = fr[lane + 32*r];
    }
}

// ---------------- route + predict fused (64 thr, 2 channels/thread) --------
__device__ __forceinline__ void mm64(const float (*in)[128][2],
                                     const float* __restrict__ W,
                                     const float* __restrict__ bias,
                                     float (*out)[128][2],
                                     int tid, bool doRelu) {
    unsigned long long acc0[6], acc1[6];
    unsigned long long b0 = packdup(bias[tid]), b1 = packdup(bias[tid + 64]);
    #pragma unroll
    for (int i = 0; i < 6; i++) { acc0[i] = b0; acc1[i] = b1; }
    const float4* wr0 = (const float4*)(W + (size_t)tid * 128);
    const float4* wr1 = (const float4*)(W + (size_t)(tid + 64) * 128);
    const unsigned long long* inu = (const unsigned long long*)in;
    for (int j4 = 0; j4 < 32; j4++) {
        float4 wa = __ldg(&wr0[j4]);
        float4 wb = __ldg(&wr1[j4]);
        unsigned long long a0 = packdup(wa.x), a1 = packdup(wa.y);
        unsigned long long a2 = packdup(wa.z), a3 = packdup(wa.w);
        unsigned long long c0 = packdup(wb.x), c1 = packdup(wb.y);
        unsigned long long c2 = packdup(wb.z), c3 = packdup(wb.w);
        #pragma unroll
        for (int l2 = 0; l2 < 6; l2++) {
            const unsigned long long* row = inu + l2*128 + 4*j4;
            unsigned long long r0 = row[0], r1 = row[1], r2 = row[2], r3 = row[3];
            dfma2(acc0[l2], r0, a0); dfma2(acc1[l2], r0, c0);
            dfma2(acc0[l2], r1, a1); dfma2(acc1[l2], r1, c1);
            dfma2(acc0[l2], r2, a2); dfma2(acc1[l2], r2, c2);
            dfma2(acc0[l2], r3, a3); dfma2(acc1[l2], r3, c3);
        }
    }
    #pragma unroll
    for (int l2 = 0; l2 < 6; l2++) {
        float v0, v1, u0, u1;
        unpack2(acc0[l2], v0, v1);
        unpack2(acc1[l2], u0, u1);
        if (doRelu) {
            v0 = fmaxf(v0, 0.f); v1 = fmaxf(v1, 0.f);
            u0 = fmaxf(u0, 0.f); u1 = fmaxf(u1, 0.f);
        }
        out[l2][tid][0] = v0;      out[l2][tid][1] = v1;
        out[l2][tid+64][0] = u0;   out[l2][tid+64][1] = u1;
    }
}

__global__ void route_kernel(const float* __restrict__ w_in, const float* __restrict__ b_in,
                             const float* __restrict__ w_out, const float* __restrict__ b_out,
                             const float* __restrict__ rt_w1, const float* __restrict__ rt_b1,
                             const float* __restrict__ rt_w2, const float* __restrict__ rt_b2,
                             const float* __restrict__ pw1, const float* __restrict__ pb1,
                             const float* __restrict__ pw2, const float* __restrict__ pb2,
                             int curBuf, int prevBuf) {
    __shared__ __align__(16) float xin[6][128][2];
    __shared__ __align__(16) float pin[6][128][2];
    __shared__ __align__(16) float qs[6][128][2];
    __shared__ __align__(16) float ks[6][128][2];
    __shared__ __align__(16) float vs[6][128][2];
    __shared__ float sc[2][4][6][6];
    int tid = threadIdx.x;                      // 64 threads
    size_t seq0 = (size_t)blockIdx.x * 2;
    const float* curr = g_wsel;
    const float* prev = (prevBuf < 0) ? g_wsel : g_rout[prevBuf];
    for (int i = tid; i < 2*6*128; i += 64) {
        int s = i / 768, r = i % 768;
        ((float*)xin)[r*2 + s] = curr[(seq0 + s)*768 + r];
        ((float*)pin)[r*2 + s] = prev[(seq0 + s)*768 + r];
    }
    __syncthreads();
    mm64(xin, w_in,            b_in,        qs, tid, false);
    mm64(pin, w_in + 128*128,  b_in + 128,  ks, tid, false);
    mm64(pin, w_in + 256*128,  b_in + 256,  vs, tid, false);
    __syncthreads();
    int warp = tid >> 5, lane = tid & 31;
    for (int pp = warp; pp < 8; pp += 2) {
        int s = pp >> 2, h = pp & 3;
        for (int e = lane; e < 36; e += 32) {
            int lq = e / 6, lk = e % 6;
            float d = 0.f;
            #pragma unroll
            for (int dd = 0; dd < 32; dd++)
                d += qs[lq][h*32 + dd][s] * ks[lk][h*32 + dd][s];
            sc[s][h][lq][lk] = d / 5.656854249492381f;
        }
        __syncwarp();
        if (lane < 6) {
            float mx = -CUDART_INF_F;
            #pragma unroll
            for (int j = 0; j < 6; j++) mx = fmaxf(mx, sc[s][h][lane][j]);
            float ex[6]; float sum = 0.f;
            #pragma unroll
            for (int j = 0; j < 6; j++) { ex[j] = expf(sc[s][h][lane][j] - mx); sum += ex[j]; }
            #pragma unroll
            for (int j = 0; j < 6; j++) sc[s][h][lane][j] = ex[j] / sum;
        }
        __syncwarp();
        for (int lq = 0; lq < 6; lq++) {
            float o = 0.f;
            #pragma unroll
            for (int j = 0; j < 6; j++) o += sc[s][h][lq][j] * vs[j][h*32 + lane][s];
            xin[lq][h*32 + lane][s] = o;
        }
    }
    __syncthreads();
    mm64(xin, w_out, b_out, pin, tid, false);
    __syncthreads();
    mm64(pin, rt_w1, rt_b1, qs, tid, true);
    __syncthreads();
    mm64(qs, rt_w2, rt_b2, ks, tid, false);
    __syncthreads();
    float* dst = g_rout[curBuf] + seq0*768;
    for (int i = tid; i < 2*6*128; i += 64) {
        int s = i / 768, r = i % 768;
        dst[(size_t)s*768 + r] = ((float*)ks)[r*2 + s];
    }
    // ---- fused predict head ----
    float* xv = (float*)qs;    // x: [2][256]
    float* hv = (float*)vs;    // h: [2][64]
    for (int c = tid; c < 128; c += 64) {
        #pragma unroll
        for (int s = 0; s < 2; s++) {
            float cent = ks[0][c][s];
            float sum = 0.f;
            #pragma unroll
            for (int l2 = 1; l2 < 6; l2++) sum += (ks[l2][c][s] - cent);
            xv[s*256 + c]       = sum * (1.0f / 5.0f);
            xv[s*256 + 128 + c] = cent;
        }
    }
    __syncthreads();
    #pragma unroll
    for (int s = 0; s < 2; s++) {
        int j = tid;
        float acc = pb1[j];
        const float4* wr = (const float4*)(pw1 + (size_t)j * 256);
        const float4* xr = (const float4*)(xv + s*256);
        #pragma unroll 8
        for (int j4 = 0; j4 < 64; j4++) {
            float4 wv = wr[j4];
            float4 x4 = xr[j4];
            acc += wv.x*x4.x + wv.y*x4.y + wv.z*x4.z + wv.w*x4.w;
        }
        hv[s*64 + j] = fmaxf(acc, 0.f);
    }
    __syncthreads();
    if (tid < 6) {
        int s = tid / 3, o = tid % 3;
        float acc = pb2[o];
        const float* wr = pw2 + o * 64;
        const float* hh = hv + s*64;
        #pragma unroll 8
        for (int j = 0; j < 64; j++) acc += wr[j] * hh[j];
        g_disp[(seq0 + s)*3 + o] = tanhf(acc);
    }
}

// ---------------- deterministic duplicate-aware scatter-add -----------------
__global__ void scatter_kernel(const int* __restrict__ start) {
    int gid = blockIdx.x * blockDim.x + threadIdx.x;
    bbox_reset(gid);
    if (gid >= NB*NM) return;
    int b = gid >> 9, m = gid & 511;
    int n = start[gid];
    const int* sb = start + b * NM;
    for (int j = 0; j < m; j++) if (sb[j] == n) return;
    float sx = 0.f, sy = 0.f, sz = 0.f;
    for (int j = m; j < NM; j++) {
        if (sb[j] == n) {
            const float* d = g_disp + (size_t)(b*NM + j) * 3;
            sx += d[0]; sy += d[1]; sz += d[2];
        }
    }
    float* p = g_pos4 + ((size_t)b*NN + n) * 4;
    p[0] += sx; p[1] += sy; p[2] += sz;
}

__global__ void finalize_kernel(float* __restrict__ out) {
    int i = blockIdx.x * blockDim.x + threadIdx.x;
    if (i < NB*NN) {
        out[i*3+0] = g_pos4[(size_t)i*4+0];
        out[i*3+1] = g_pos4[(size_t)i*4+1];
        out[i*3+2] = g_pos4[(size_t)i*4+2];
    }
}

// ---------------- host driver ----------------------------------------------
extern "C" void kernel_launch(void* const* d_in, const int* in_sizes, int n_in,
                              void* d_out, int out_size) {
    (void)in_sizes; (void)n_in; (void)out_size;
    const float* xyz      = (const float*)d_in[0];
    const int*   start    = (const int*)  d_in[1];
    const float* gumbel   = (const float*)d_in[2];
    const float* enc_w1   = (const float*)d_in[3];
    const float* enc_b1   = (const float*)d_in[4];
    const float* enc_w2   = (const float*)d_in[5];
    const float* enc_b2   = (const float*)d_in[6];
    const float* beta_w   = (const float*)d_in[7];
    const float* beta_b   = (const float*)d_in[8];
    const float* gamma_w  = (const float*)d_in[9];
    const float* gamma_b  = (const float*)d_in[10];
    const float* attn_w_in  = (const float*)d_in[11];
    const float* attn_b_in  = (const float*)d_in[12];
    const float* attn_w_out = (const float*)d_in[13];
    const float* attn_b_out = (const float*)d_in[14];
    const float* rt_w1    = (const float*)d_in[15];
    const float* rt_b1    = (const float*)d_in[16];
    const float* rt_w2    = (const float*)d_in[17];
    const float* rt_b2    = (const float*)d_in[18];
    const float* pred_w1  = (const float*)d_in[19];
    const float* pred_b1  = (const float*)d_in[20];
    const float* pred_w2  = (const float*)d_in[21];
    const float* pred_b2  = (const float*)d_in[22];

    init_pos_kernel<<<(NB*NN + 127)/128, 128>>>(xyz);
    encode_kernel<<<NB*NN/4, 128>>>(xyz, enc_w1, enc_b1, enc_w2, enc_b2);
    proj_kernel<<<NB*NN/16, 128>>>(beta_w, beta_b, gamma_w, gamma_b);

    for (int t = 0; t < NSTEPS; t++) {
        int cur = t & 1;
        int prv = (t == 0) ? -1 : (1 - cur);
        gridprep_kernel<<<256, 256>>>();
        hist_kernel<<<256, 256>>>();
        scan_kernel<<<NB, 1024>>>();
        scatterpts_kernel<<<256, 256>>>();
        knn_step_kernel<<<NB*NM/4, 128>>>(start, gumbel, t);
        route_kernel<<<NB*NM/2, 64>>>(attn_w_in, attn_b_in, attn_w_out, attn_b_out,
                                      rt_w1, rt_b1, rt_w2, rt_b2,
                                      pred_w1, pred_b1, pred_w2, pred_b2, cur, prv);
        scatter_kernel<<<(NB*NM + 127)/128, 128>>>(start);
    }
    finalize_kernel<<<(NB*NN + 127)/128, 128>>>((float*)d_out);
}

// round 10
// speedup vs baseline: 1.3551x; 1.3551x over previous
#include <cuda_runtime.h>
#include <math_constants.h>

#define NB 4
#define NN 16384
#define NM 512
#define NC 128
#define NK 16
#define NL 6
#define NSTEPS 5

// ---------------- scratch (device globals: no allocations allowed) ----------
__device__ float g_feats[NB*NN*NC];
__device__ float g_Qf[NB*NN*NC];
__device__ float g_Gf[NB*NN*NC];
__device__ __align__(16) float g_pos4[NB*NN*4];
__device__ float g_wsel[NB*NM*NL*NC];
__device__ float g_rout[2][NB*NM*NL*NC];
__device__ float g_disp[NB*NM*3];

// ---------------- f32x2 packed helpers --------------------------------------
__device__ __forceinline__ void dfma2(unsigned long long& d,
                                      unsigned long long a,
                                      unsigned long long b) {
    asm("fma.rn.f32x2 %0, %1, %2, %0;" : "+l"(d) : "l"(a), "l"(b));
}
__device__ __forceinline__ unsigned long long dadd2(unsigned long long a,
                                                    unsigned long long b) {
    unsigned long long r;
    asm("add.rn.f32x2 %0, %1, %2;" : "=l"(r) : "l"(a), "l"(b));
    return r;
}
__device__ __forceinline__ unsigned long long dmul2(unsigned long long a,
                                                    unsigned long long b) {
    unsigned long long r;
    asm("mul.rn.f32x2 %0, %1, %2;" : "=l"(r) : "l"(a), "l"(b));
    return r;
}
__device__ __forceinline__ unsigned long long dfmar2(unsigned long long a,
                                                     unsigned long long b,
                                                     unsigned long long c) {
    unsigned long long r;
    asm("fma.rn.f32x2 %0, %1, %2, %3;" : "=l"(r) : "l"(a), "l"(b), "l"(c));
    return r;
}
__device__ __forceinline__ unsigned long long packdup(float w) {
    unsigned long long r;
    asm("mov.b64 %0, {%1, %1};" : "=l"(r) : "f"(w));
    return r;
}
__device__ __forceinline__ void unpack2(unsigned long long a, float& lo, float& hi) {
    asm("mov.b64 {%0, %1}, %2;" : "=f"(lo), "=f"(hi) : "l"(a));
}

// ---------------- init: padded positions -------------------------------------
__global__ void init_pos_kernel(const float* __restrict__ xyz) {
    int i = blockIdx.x * blockDim.x + threadIdx.x;
    if (i < NB*NN) {
        float x = xyz[i*3+0], y = xyz[i*3+1], z = xyz[i*3+2];
        *(float4*)&g_pos4[(size_t)i*4] = make_float4(x, y, z, 0.f);
    }
}

// ---------------- encoder ---------------------------------------------------
__global__ void encode_kernel(const float* __restrict__ xyz,
                              const float* __restrict__ w1, const float* __restrict__ b1,
                              const float* __restrict__ w2, const float* __restrict__ b2) {
    __shared__ float h[4][64];
    int tid = threadIdx.x;
    int p0 = blockIdx.x * 4;
    for (int i = tid; i < 4*64; i += 128) {
        int pt = i >> 6, j = i & 63;
        const float* x = xyz + (size_t)(p0 + pt) * 3;
        float v = b1[j] + w1[j*3+0]*x[0] + w1[j*3+1]*x[1] + w1[j*3+2]*x[2];
        h[pt][j] = fmaxf(v, 0.f);
    }
    __syncthreads();
    float acc[4];
    #pragma unroll
    for (int p = 0; p < 4; p++) acc[p] = b2[tid];
    const float4* wr = (const float4*)(w2 + (size_t)tid * 64);
    #pragma unroll
    for (int j4 = 0; j4 < 16; j4++) {
        float4 w = wr[j4];
        #pragma unroll
        for (int p = 0; p < 4; p++) {
            float4 hv = *(const float4*)&h[p][4*j4];
            acc[p] += w.x*hv.x + w.y*hv.y + w.z*hv.z + w.w*hv.w;
        }
    }
    #pragma unroll
    for (int p = 0; p < 4; p++)
        g_feats[(size_t)(p0 + p) * NC + tid] = acc[p];
}

// ---------------- beta/gamma projections (f32x2 point-pairs) ----------------
__global__ void proj_kernel(const float* __restrict__ bw, const float* __restrict__ bb,
                            const float* __restrict__ gw, const float* __restrict__ gb) {
    __shared__ __align__(8) float xs[128*16];      // xs[ch*16 + p]
    int c = threadIdx.x;                           // 128 threads
    size_t base = (size_t)blockIdx.x * 16 * 128;
    for (int i = c; i < 16*128; i += 128) {
        int p = i >> 7, ch = i & 127;
        xs[ch*16 + p] = g_feats[base + i];
    }
    __syncthreads();
    unsigned long long accQ[8], accG[8];
    unsigned long long bq = packdup(bb[c]), bg = packdup(gb[c]);
    #pragma unroll
    for (int p = 0; p < 8; p++) { accQ[p] = bq; accG[p] = bg; }
    const float4* wq = (const float4*)(bw + (size_t)c * 128);
    const float4* wg = (const float4*)(gw + (size_t)c * 128);
    for (int j4 = 0; j4 < 32; j4++) {
        float4 a = wq[j4];
        float4 g = wg[j4];
        float aa[4] = {a.x, a.y, a.z, a.w};
        float gg2[4] = {g.x, g.y, g.z, g.w};
        #pragma unroll
        for (int jj = 0; jj < 4; jj++) {
            int ch = 4*j4 + jj;
            unsigned long long wa = packdup(aa[jj]);
            unsigned long long wgv = packdup(gg2[jj]);
            const unsigned long long* x2 = (const unsigned long long*)&xs[ch*16];
            #pragma unroll
            for (int p = 0; p < 8; p++) {
                dfma2(accQ[p], x2[p], wa);
                dfma2(accG[p], x2[p], wgv);
            }
        }
    }
    #pragma unroll
    for (int p = 0; p < 8; p++) {
        float q0, q1, g0, g1;
        unpack2(accQ[p], q0, q1);
        unpack2(accG[p], g0, g1);
        g_Qf[base + (size_t)(2*p)*128 + c]   = q0;
        g_Qf[base + (size_t)(2*p+1)*128 + c] = q1;
        g_Gf[base + (size_t)(2*p)*128 + c]   = g0;
        g_Gf[base + (size_t)(2*p+1)*128 + c] = g1;
    }
}

// ---------------- KNN: warp-distributed sorted top-17 insert ----------------
__device__ __forceinline__ void kinsert(unsigned bal, float d, int ci,
                                        float& ld, int& li, float& tau, int lane) {
    do {
        int src = __ffs(bal) - 1; bal &= bal - 1;
        float dc = __shfl_sync(0xffffffffu, d, src);
        int   ic = __shfl_sync(0xffffffffu, ci, src);
        float pd = __shfl_up_sync(0xffffffffu, ld, 1);
        int   pi = __shfl_up_sync(0xffffffffu, li, 1);
        unsigned lt = __ballot_sync(0xffffffffu,
                (ld < dc) || ((ld == dc) && (li < ic))) & 0x1FFFFu;
        int pn = __popc(lt);
        if (lane < 17) {
            if (lane == pn)      { ld = dc; li = ic; }
            else if (lane > pn)  { ld = pd; li = pi; }
        }
    } while (bal);
    tau = __shfl_sync(0xffffffffu, ld, 16);
}

// ---------------- fused per-step selector ------------------------------------
// 512 blocks x 256 threads. 4 queries/block; each query scanned by TWO warps
// (halves of the candidate set), exact merge of the two sorted top-17 lists,
// then logits + gumbel argmax by the primary warp. Tiles staged in SoA smem,
// 2 candidates per lane per iteration via packed f32x2.
#define KTPB 256
#define KQB 4
#define KTILE 2048

__global__ __launch_bounds__(KTPB, 4)
void knn_step_kernel(const int* __restrict__ start,
                     const float* __restrict__ gumbel, int t) {
    __shared__ __align__(8) float sx[KTILE], sy[KTILE], sz[KTILE];
    __shared__ unsigned long long mkeys[KQB][2][17];
    __shared__ int sknn[KQB][NK];
    __shared__ int snext[KQB];
    int tid = threadIdx.x, warp = tid >> 5, lane = tid & 31;
    int q = warp & 3, half = warp >> 2;
    int b = blockIdx.x / (NM/KQB);
    int m = (blockIdx.x % (NM/KQB)) * KQB + q;
    int gw = b*NM + m;
    int qidx = start[gw];
    const float4* pos = (const float4*)(g_pos4 + (size_t)b*NN*4);
    const float* Gf = g_Gf + (size_t)b*NN*NC;

    if (half == 0) {   // walk[0] = feats[start]
        const float* fr = g_feats + ((size_t)b*NN + qidx) * NC;
        float* wr = g_wsel + (size_t)gw * NL * NC;
        #pragma unroll
        for (int r = 0; r < 4; r++) wr[lane + 32*r] = fr[lane + 32*r];
    }

    for (int l = 0; l < NL-1; l++) {
        float4 qp = pos[qidx];
        unsigned long long nqx = packdup(-qp.x);
        unsigned long long nqy = packdup(-qp.y);
        unsigned long long nqz = packdup(-qp.z);
        float ld = CUDART_INF_F;
        int   li = 0x7FFFFFFF;
        float tau = CUDART_INF_F;

        for (int tb = 0; tb < NN/KTILE; tb++) {
            __syncthreads();
            const float4* srcp = pos + tb*KTILE;
            for (int i = tid; i < KTILE; i += KTPB) {
                float4 p = srcp[i];
                sx[i] = p.x; sy[i] = p.y; sz[i] = p.z;
            }
            __syncthreads();
            const unsigned long long* sx2 = (const unsigned long long*)sx;
            const unsigned long long* sy2 = (const unsigned long long*)sy;
            const unsigned long long* sz2 = (const unsigned long long*)sz;
            int base = tb * KTILE;
            for (int pi = half*32 + lane; pi < KTILE/2; pi += 64) {
                unsigned long long dxp = dadd2(sx2[pi], nqx);
                unsigned long long dyp = dadd2(sy2[pi], nqy);
                unsigned long long dzp = dadd2(sz2[pi], nqz);
                unsigned long long dp = dmul2(dxp, dxp);
                dp = dfmar2(dyp, dyp, dp);
                dp = dfmar2(dzp, dzp, dp);     // = dz*dz + (dy*dy + dx*dx), per-lane IEEE
                float d0, d1;
                unpack2(dp, d0, d1);
                int c0 = base + 2*pi;
                unsigned bal0 = __ballot_sync(0xffffffffu, d0 < tau);
                if (bal0) kinsert(bal0, d0, c0, ld, li, tau, lane);
                unsigned bal1 = __ballot_sync(0xffffffffu, d1 < tau);
                if (bal1) kinsert(bal1, d1, c0 + 1, ld, li, tau, lane);
            }
        }
        // publish sorted half-lists as lex (d_bits, idx) keys
        if (lane < 17)
            mkeys[q][half][lane] =
                ((unsigned long long)__float_as_uint(ld) << 32) | (unsigned)li;
        __syncthreads();

        if (half == 0) {
            // exact merge: top-17 of the 34 unique keys
            unsigned long long k0 = (lane < 17) ? mkeys[q][0][lane] : ~0ull;
            unsigned long long k1 = (lane < 17) ? mkeys[q][1][lane] : ~0ull;
            unsigned long long mykey = ~0ull;
            for (int j = 0; j < 17; j++) {
                unsigned long long local = (k0 < k1) ? k0 : k1;
                unsigned long long mv = local;
                #pragma unroll
                for (int off = 16; off; off >>= 1) {
                    unsigned long long o = __shfl_xor_sync(0xffffffffu, mv, off);
                    mv = (o < mv) ? o : mv;
                }
                if (local == mv) { if (k0 == mv) k0 = ~0ull; else k1 = ~0ull; }
                if (lane == j) mykey = mv;
            }
            // entry 0 = minimum (self by lex); neighbors = entries 1..16
            if (lane >= 1 && lane < 17)
                sknn[q][lane - 1] = (int)(unsigned)(mykey & 0xFFFFFFFFull);
            __syncwarp();

            // logits + gumbel argmax
            const float* Q = g_Qf + ((size_t)b*NN + qidx) * NC;
            float qv0 = Q[lane], qv1 = Q[lane+32], qv2 = Q[lane+64], qv3 = Q[lane+96];
            float pk[16];
            #pragma unroll
            for (int k = 0; k < 16; k++) {
                const float* gr = Gf + (size_t)sknn[q][k] * NC;
                pk[k] = qv0*gr[lane] + qv1*gr[lane+32] + qv2*gr[lane+64] + qv3*gr[lane+96];
            }
            #pragma unroll
            for (int k = 0; k < 16; k++) {
                #pragma unroll
                for (int off = 16; off; off >>= 1)
                    pk[k] += __shfl_xor_sync(0xffffffffu, pk[k], off);
            }
            const float* gm = gumbel + ((((size_t)t*(NL-1) + l)*NB + b)*NM + m) * NK;
            float best = -CUDART_INF_F; int bk = 0;
            #pragma unroll
            for (int k = 0; k < 16; k++) {
                float s = pk[k] / 11.313708498984761f + gm[k];   // /sqrt(128)
                if (s > best) { best = s; bk = k; }
            }
            int nidx = sknn[q][bk];
            if (lane == 0) snext[q] = nidx;
            const float* fr = g_feats + ((size_t)b*NN + nidx) * NC;
            float* wr = g_wsel + ((size_t)gw * NL + (l + 1)) * NC;
            #pragma unroll
            for (int r = 0; r < 4; r++) wr[lane + 32*r] = fr[lane + 32*r];
        }
        __syncthreads();
        qidx = snext[q];
    }
}

// ---------------- route + predict fused (64 thr, 2 channels/thread) --------
__device__ __forceinline__ void mm64(const float (*in)[128][2],
                                     const float* __restrict__ W,
                                     const float* __restrict__ bias,
                                     float (*out)[128][2],
                                     int tid, bool doRelu) {
    unsigned long long acc0[6], acc1[6];
    unsigned long long b0 = packdup(bias[tid]), b1 = packdup(bias[tid + 64]);
    #pragma unroll
    for (int i = 0; i < 6; i++) { acc0[i] = b0; acc1[i] = b1; }
    const float4* wr0 = (const float4*)(W + (size_t)tid * 128);
    const float4* wr1 = (const float4*)(W + (size_t)(tid + 64) * 128);
    const unsigned long long* inu = (const unsigned long long*)in;
    for (int j4 = 0; j4 < 32; j4++) {
        float4 wa = __ldg(&wr0[j4]);
        float4 wb = __ldg(&wr1[j4]);
        unsigned long long a0 = packdup(wa.x), a1 = packdup(wa.y);
        unsigned long long a2 = packdup(wa.z), a3 = packdup(wa.w);
        unsigned long long c0 = packdup(wb.x), c1 = packdup(wb.y);
        unsigned long long c2 = packdup(wb.z), c3 = packdup(wb.w);
        #pragma unroll
        for (int l2 = 0; l2 < 6; l2++) {
            const unsigned long long* row = inu + l2*128 + 4*j4;
            unsigned long long r0 = row[0], r1 = row[1], r2 = row[2], r3 = row[3];
            dfma2(acc0[l2], r0, a0); dfma2(acc1[l2], r0, c0);
            dfma2(acc0[l2], r1, a1); dfma2(acc1[l2], r1, c1);
            dfma2(acc0[l2], r2, a2); dfma2(acc1[l2], r2, c2);
            dfma2(acc0[l2], r3, a3); dfma2(acc1[l2], r3, c3);
        }
    }
    #pragma unroll
    for (int l2 = 0; l2 < 6; l2++) {
        float v0, v1, u0, u1;
        unpack2(acc0[l2], v0, v1);
        unpack2(acc1[l2], u0, u1);
        if (doRelu) {
            v0 = fmaxf(v0, 0.f); v1 = fmaxf(v1, 0.f);
            u0 = fmaxf(u0, 0.f); u1 = fmaxf(u1, 0.f);
        }
        out[l2][tid][0] = v0;      out[l2][tid][1] = v1;
        out[l2][tid+64][0] = u0;   out[l2][tid+64][1] = u1;
    }
}

__global__ void route_kernel(const float* __restrict__ w_in, const float* __restrict__ b_in,
                             const float* __restrict__ w_out, const float* __restrict__ b_out,
                             const float* __restrict__ rt_w1, const float* __restrict__ rt_b1,
                             const float* __restrict__ rt_w2, const float* __restrict__ rt_b2,
                             const float* __restrict__ pw1, const float* __restrict__ pb1,
                             const float* __restrict__ pw2, const float* __restrict__ pb2,
                             int curBuf, int prevBuf) {
    __shared__ __align__(16) float xin[6][128][2];
    __shared__ __align__(16) float pin[6][128][2];
    __shared__ __align__(16) float qs[6][128][2];
    __shared__ __align__(16) float ks[6][128][2];
    __shared__ __align__(16) float vs[6][128][2];
    __shared__ float sc[2][4][6][6];
    int tid = threadIdx.x;                      // 64 threads
    size_t seq0 = (size_t)blockIdx.x * 2;
    const float* curr = g_wsel;
    const float* prev = (prevBuf < 0) ? g_wsel : g_rout[prevBuf];
    for (int i = tid; i < 2*6*128; i += 64) {
        int s = i / 768, r = i % 768;
        ((float*)xin)[r*2 + s] = curr[(seq0 + s)*768 + r];
        ((float*)pin)[r*2 + s] = prev[(seq0 + s)*768 + r];
    }
    __syncthreads();
    mm64(xin, w_in,            b_in,        qs, tid, false);
    mm64(pin, w_in + 128*128,  b_in + 128,  ks, tid, false);
    mm64(pin, w_in + 256*128,  b_in + 256,  vs, tid, false);
    __syncthreads();
    int warp = tid >> 5, lane = tid & 31;
    for (int pp = warp; pp < 8; pp += 2) {
        int s = pp >> 2, h = pp & 3;
        for (int e = lane; e < 36; e += 32) {
            int lq = e / 6, lk = e % 6;
            float d = 0.f;
            #pragma unroll
            for (int dd = 0; dd < 32; dd++)
                d += qs[lq][h*32 + dd][s] * ks[lk][h*32 + dd][s];
            sc[s][h][lq][lk] = d / 5.656854249492381f;
        }
        __syncwarp();
        if (lane < 6) {
            float mx = -CUDART_INF_F;
            #pragma unroll
            for (int j = 0; j < 6; j++) mx = fmaxf(mx, sc[s][h][lane][j]);
            float ex[6]; float sum = 0.f;
            #pragma unroll
            for (int j = 0; j < 6; j++) { ex[j] = expf(sc[s][h][lane][j] - mx); sum += ex[j]; }
            #pragma unroll
            for (int j = 0; j < 6; j++) sc[s][h][lane][j] = ex[j] / sum;
        }
        __syncwarp();
        for (int lq = 0; lq < 6; lq++) {
            float o = 0.f;
            #pragma unroll
            for (int j = 0; j < 6; j++) o += sc[s][h][lq][j] * vs[j][h*32 + lane][s];
            xin[lq][h*32 + lane][s] = o;
        }
    }
    __syncthreads();
    mm64(xin, w_out, b_out, pin, tid, false);
    __syncthreads();
    mm64(pin, rt_w1, rt_b1, qs, tid, true);
    __syncthreads();
    mm64(qs, rt_w2, rt_b2, ks, tid, false);
    __syncthreads();
    float* dst = g_rout[curBuf] + seq0*768;
    for (int i = tid; i < 2*6*128; i += 64) {
        int s = i / 768, r = i % 768;
        dst[(size_t)s*768 + r] = ((float*)ks)[r*2 + s];
    }
    // ---- fused predict head ----
    float* xv = (float*)qs;    // x: [2][256]
    float* hv = (float*)vs;    // h: [2][64]
    for (int c = tid; c < 128; c += 64) {
        #pragma unroll
        for (int s = 0; s < 2; s++) {
            float cent = ks[0][c][s];
            float sum = 0.f;
            #pragma unroll
            for (int l2 = 1; l2 < 6; l2++) sum += (ks[l2][c][s] - cent);
            xv[s*256 + c]       = sum * (1.0f / 5.0f);
            xv[s*256 + 128 + c] = cent;
        }
    }
    __syncthreads();
    #pragma unroll
    for (int s = 0; s < 2; s++) {
        int j = tid;
        float acc = pb1[j];
        const float4* wr = (const float4*)(pw1 + (size_t)j * 256);
        const float4* xr = (const float4*)(xv + s*256);
        #pragma unroll 8
        for (int j4 = 0; j4 < 64; j4++) {
            float4 wv = wr[j4];
            float4 x4 = xr[j4];
            acc += wv.x*x4.x + wv.y*x4.y + wv.z*x4.z + wv.w*x4.w;
        }
        hv[s*64 + j] = fmaxf(acc, 0.f);
    }
    __syncthreads();
    if (tid < 6) {
        int s = tid / 3, o = tid % 3;
        float acc = pb2[o];
        const float* wr = pw2 + o * 64;
        const float* hh = hv + s*64;
        #pragma unroll 8
        for (int j = 0; j < 64; j++) acc += wr[j] * hh[j];
        g_disp[(seq0 + s)*3 + o] = tanhf(acc);
    }
}

// ---------------- deterministic duplicate-aware scatter-add -----------------
__global__ void scatter_kernel(const int* __restrict__ start) {
    int gid = blockIdx.x * blockDim.x + threadIdx.x;
    if (gid >= NB*NM) return;
    int b = gid >> 9, m = gid & 511;
    int n = start[gid];
    const int* sb = start + b * NM;
    for (int j = 0; j < m; j++) if (sb[j] == n) return;
    float sx = 0.f, sy = 0.f, sz = 0.f;
    for (int j = m; j < NM; j++) {
        if (sb[j] == n) {
            const float* d = g_disp + (size_t)(b*NM + j) * 3;
            sx += d[0]; sy += d[1]; sz += d[2];
        }
    }
    float* p = g_pos4 + ((size_t)b*NN + n) * 4;
    p[0] += sx; p[1] += sy; p[2] += sz;
}

__global__ void finalize_kernel(float* __restrict__ out) {
    int i = blockIdx.x * blockDim.x + threadIdx.x;
    if (i < NB*NN) {
        out[i*3+0] = g_pos4[(size_t)i*4+0];
        out[i*3+1] = g_pos4[(size_t)i*4+1];
        out[i*3+2] = g_pos4[(size_t)i*4+2];
    }
}

// ---------------- host driver ----------------------------------------------
extern "C" void kernel_launch(void* const* d_in, const int* in_sizes, int n_in,
                              void* d_out, int out_size) {
    (void)in_sizes; (void)n_in; (void)out_size;
    const float* xyz      = (const float*)d_in[0];
    const int*   start    = (const int*)  d_in[1];
    const float* gumbel   = (const float*)d_in[2];
    const float* enc_w1   = (const float*)d_in[3];
    const float* enc_b1   = (const float*)d_in[4];
    const float* enc_w2   = (const float*)d_in[5];
    const float* enc_b2   = (const float*)d_in[6];
    const float* beta_w   = (const float*)d_in[7];
    const float* beta_b   = (const float*)d_in[8];
    const float* gamma_w  = (const float*)d_in[9];
    const float* gamma_b  = (const float*)d_in[10];
    const float* attn_w_in  = (const float*)d_in[11];
    const float* attn_b_in  = (const float*)d_in[12];
    const float* attn_w_out = (const float*)d_in[13];
    const float* attn_b_out = (const float*)d_in[14];
    const float* rt_w1    = (const float*)d_in[15];
    const float* rt_b1    = (const float*)d_in[16];
    const float* rt_w2    = (const float*)d_in[17];
    const float* rt_b2    = (const float*)d_in[18];
    const float* pred_w1  = (const float*)d_in[19];
    const float* pred_b1  = (const float*)d_in[20];
    const float* pred_w2  = (const float*)d_in[21];
    const float* pred_b2  = (const float*)d_in[22];

    init_pos_kernel<<<(NB*NN + 127)/128, 128>>>(xyz);
    encode_kernel<<<NB*NN/4, 128>>>(xyz, enc_w1, enc_b1, enc_w2, enc_b2);
    proj_kernel<<<NB*NN/16, 128>>>(beta_w, beta_b, gamma_w, gamma_b);

    for (int t = 0; t < NSTEPS; t++) {
        int cur = t & 1;
        int prv = (t == 0) ? -1 : (1 - cur);
        knn_step_kernel<<<NB*NM/KQB, KTPB>>>(start, gumbel, t);
        route_kernel<<<NB*NM/2, 64>>>(attn_w_in, attn_b_in, attn_w_out, attn_b_out,
                                      rt_w1, rt_b1, rt_w2, rt_b2,
                                      pred_w1, pred_b1, pred_w2, pred_b2, cur, prv);
        scatter_kernel<<<(NB*NM + 127)/128, 128>>>(start);
    }
    finalize_kernel<<<(NB*NN + 127)/128, 128>>>((float*)d_out);
}